// round 1
// baseline (speedup 1.0000x reference)
#include <cuda_runtime.h>

#define NMAX 50000
#define EMAX 800000
#define DIM 64
#define NGR 512

// ---------------- scratch (device globals: no allocation allowed) -----------
__device__ int   g_is64;
__device__ int   g_deg[NMAX];        // per-target real-edge count
__device__ int   g_off[NMAX + 1];    // CSR offsets
__device__ int   g_cur[NMAX];        // scatter cursors
__device__ float g_dinv[NMAX];       // 1/sqrt(deg+1)
__device__ int   g_row[EMAX];
__device__ int   g_col[EMAX];
__device__ int   g_src[EMAX];        // CSR-sorted source node
__device__ float g_nrm[EMAX];        // CSR-sorted edge norm
__device__ float g_h[NMAX * DIM];    // GEMM output (pre-aggregation)
__device__ float g_f[NMAX * DIM];    // aggregated features (next layer input)
__device__ float g_gsum[NGR];
__device__ float g_gcnt[NGR];

// ---------------- K0: zero scratch + detect index dtype ---------------------
__global__ void k_zero_detect(const void* ei, int n) {
    int i = blockIdx.x * blockDim.x + threadIdx.x;
    if (i < n) { g_deg[i] = 0; g_cur[i] = 0; }
    if (i < NGR) { g_gsum[i] = 0.f; g_gcnt[i] = 0.f; }
    if (i == 0) {
        // int64 little-endian: high 32-bit word of every (small, positive)
        // index is 0. For int32 data the odd words are uniform in [0,50000).
        const int* p = (const int*)ei;
        int is64 = 1;
        for (int k = 0; k < 512; k++) {
            if (p[2 * k + 1] != 0) { is64 = 0; break; }
        }
        g_is64 = is64;
    }
}

// ---------------- K1: convert indices + degree histogram --------------------
__global__ void k_hist(const void* ei, int E) {
    int e = blockIdx.x * blockDim.x + threadIdx.x;
    if (e >= E) return;
    int r, c;
    if (g_is64) {
        const long long* p = (const long long*)ei;
        r = (int)p[e]; c = (int)p[E + e];
    } else {
        const int* p = (const int*)ei;
        r = p[e]; c = p[E + e];
    }
    g_row[e] = r;
    g_col[e] = c;
    atomicAdd(&g_deg[c], 1);
}

// ---------------- K2: dinv + per-graph node counts ---------------------------
__global__ void k_dinv(const void* batch, int n) {
    int i = blockIdx.x * blockDim.x + threadIdx.x;
    if (i >= n) return;
    g_dinv[i] = rsqrtf((float)(g_deg[i] + 1));   // +1 = self-loop
    int b = g_is64 ? (int)((const long long*)batch)[i]
                   : ((const int*)batch)[i];
    atomicAdd(&g_gcnt[b], 1.0f);
}

// ---------------- K3: single-block exclusive scan of g_deg -> g_off ---------
__global__ void k_scan(int n) {
    __shared__ int sh[1024];
    const int tid = threadIdx.x;
    const int chunk = (n + 1023) / 1024;
    const int beg = tid * chunk;
    const int end = min(beg + chunk, n);
    int s = 0;
    for (int i = beg; i < end; i++) s += g_deg[i];
    sh[tid] = s;
    __syncthreads();
    // Hillis-Steele inclusive scan over 1024 partials
    for (int d = 1; d < 1024; d <<= 1) {
        int v = (tid >= d) ? sh[tid - d] : 0;
        __syncthreads();
        sh[tid] += v;
        __syncthreads();
    }
    int pre = (tid == 0) ? 0 : sh[tid - 1];
    for (int i = beg; i < end; i++) {
        g_off[i] = pre;
        pre += g_deg[i];
    }
    if (beg < n && end == n) g_off[n] = pre;
}

// ---------------- K4: scatter edges into CSR slots ---------------------------
__global__ void k_csr(int E) {
    int e = blockIdx.x * blockDim.x + threadIdx.x;
    if (e >= E) return;
    int c = g_col[e];
    int r = g_row[e];
    int pos = g_off[c] + atomicAdd(&g_cur[c], 1);
    g_src[pos] = r;
    g_nrm[pos] = g_dinv[r] * g_dinv[c];
}

// ---------------- K5: GEMM  H = X @ W  (X: [n,64], W: [64,64]) --------------
// 256 threads, 64 nodes per block. Thread tile: 2 nodes x 8 cols.
__global__ __launch_bounds__(256) void k_gemm(const float* __restrict__ X,
                                              const float* __restrict__ W,
                                              float* __restrict__ H, int n) {
    __shared__ float xs[64][65];   // padded: conflict-free column reads
    __shared__ float ws[64][64];
    const int tid = threadIdx.x;
    const int n0 = blockIdx.x * 64;

    // stage W (4096 floats)
    for (int i = tid; i < 64 * 16; i += 256)
        ((float4*)ws)[i] = ((const float4*)W)[i];
    // stage X tile (64 rows x 16 float4)
    for (int i = tid; i < 64 * 16; i += 256) {
        int r = i >> 4, kq = (i & 15) << 2;
        int node = n0 + r;
        float4 v = (node < n) ? ((const float4*)(X + (size_t)node * DIM))[i & 15]
                              : make_float4(0.f, 0.f, 0.f, 0.f);
        xs[r][kq] = v.x; xs[r][kq + 1] = v.y; xs[r][kq + 2] = v.z; xs[r][kq + 3] = v.w;
    }
    __syncthreads();

    const int cg = tid & 7;    // 8 column groups of 8
    const int ng = tid >> 3;   // 32 node groups of 2
    float acc[2][8];
#pragma unroll
    for (int i = 0; i < 2; i++)
#pragma unroll
        for (int j = 0; j < 8; j++) acc[i][j] = 0.f;

#pragma unroll 8
    for (int k = 0; k < 64; k++) {
        float4 w0 = *(float4*)&ws[k][cg * 8];
        float4 w1 = *(float4*)&ws[k][cg * 8 + 4];
#pragma unroll
        for (int i = 0; i < 2; i++) {
            float xv = xs[ng * 2 + i][k];
            acc[i][0] += xv * w0.x; acc[i][1] += xv * w0.y;
            acc[i][2] += xv * w0.z; acc[i][3] += xv * w0.w;
            acc[i][4] += xv * w1.x; acc[i][5] += xv * w1.y;
            acc[i][6] += xv * w1.z; acc[i][7] += xv * w1.w;
        }
    }
#pragma unroll
    for (int i = 0; i < 2; i++) {
        int node = n0 + ng * 2 + i;
        if (node < n) {
            float4 o0 = make_float4(acc[i][0], acc[i][1], acc[i][2], acc[i][3]);
            float4 o1 = make_float4(acc[i][4], acc[i][5], acc[i][6], acc[i][7]);
            float4* dst = (float4*)(H + (size_t)node * DIM);
            dst[cg * 2] = o0;
            dst[cg * 2 + 1] = o1;
        }
    }
}

// ---------------- K6: gather-aggregation, one warp per node -----------------
// F[c] = relu?( b + dinv[c]^2 * H[c] + sum_e nrm[e] * H[src[e]] )
template <int RELU>
__global__ __launch_bounds__(256) void k_agg(const float* __restrict__ H,
                                             const float* __restrict__ bias,
                                             float* __restrict__ F, int n) {
    int c = (blockIdx.x * blockDim.x + threadIdx.x) >> 5;
    int lane = threadIdx.x & 31;
    if (c >= n) return;

    float2 acc = ((const float2*)bias)[lane];
    float di = g_dinv[c];
    float s = di * di;
    float2 hc = *(const float2*)(H + (size_t)c * DIM + 2 * lane);
    acc.x += s * hc.x; acc.y += s * hc.y;

    int e = g_off[c];
    const int end = g_off[c + 1];
    for (; e + 1 < end; e += 2) {
        int s0 = g_src[e], s1 = g_src[e + 1];
        float w0 = g_nrm[e], w1 = g_nrm[e + 1];
        float2 a = *(const float2*)(H + (size_t)s0 * DIM + 2 * lane);
        float2 b = *(const float2*)(H + (size_t)s1 * DIM + 2 * lane);
        acc.x += w0 * a.x + w1 * b.x;
        acc.y += w0 * a.y + w1 * b.y;
    }
    if (e < end) {
        int s0 = g_src[e];
        float w0 = g_nrm[e];
        float2 a = *(const float2*)(H + (size_t)s0 * DIM + 2 * lane);
        acc.x += w0 * a.x; acc.y += w0 * a.y;
    }
    if (RELU) { acc.x = fmaxf(acc.x, 0.f); acc.y = fmaxf(acc.y, 0.f); }
    *(float2*)(F + (size_t)c * DIM + 2 * lane) = acc;
}

// ---------------- K6f: final layer fused with lin head + pooling sums -------
__global__ __launch_bounds__(256) void k_agg_final(const float* __restrict__ H,
                                                   const float* __restrict__ bias,
                                                   const float* __restrict__ lw,
                                                   const void* __restrict__ batch,
                                                   int n) {
    int c = (blockIdx.x * blockDim.x + threadIdx.x) >> 5;
    int lane = threadIdx.x & 31;
    if (c >= n) return;

    float2 acc = ((const float2*)bias)[lane];
    float di = g_dinv[c];
    float s = di * di;
    float2 hc = *(const float2*)(H + (size_t)c * DIM + 2 * lane);
    acc.x += s * hc.x; acc.y += s * hc.y;

    int e = g_off[c];
    const int end = g_off[c + 1];
    for (; e + 1 < end; e += 2) {
        int s0 = g_src[e], s1 = g_src[e + 1];
        float w0 = g_nrm[e], w1 = g_nrm[e + 1];
        float2 a = *(const float2*)(H + (size_t)s0 * DIM + 2 * lane);
        float2 b = *(const float2*)(H + (size_t)s1 * DIM + 2 * lane);
        acc.x += w0 * a.x + w1 * b.x;
        acc.y += w0 * a.y + w1 * b.y;
    }
    if (e < end) {
        int s0 = g_src[e];
        float w0 = g_nrm[e];
        float2 a = *(const float2*)(H + (size_t)s0 * DIM + 2 * lane);
        acc.x += w0 * a.x; acc.y += w0 * a.y;
    }

    float2 w = ((const float2*)lw)[lane];
    float p = acc.x * w.x + acc.y * w.y;
#pragma unroll
    for (int o = 16; o; o >>= 1) p += __shfl_xor_sync(0xFFFFFFFFu, p, o);
    if (lane == 0) {
        int b = g_is64 ? (int)((const long long*)batch)[c]
                       : ((const int*)batch)[c];
        atomicAdd(&g_gsum[b], p);
    }
}

// ---------------- K7: finalize output ---------------------------------------
__global__ void k_final(const float* __restrict__ lb, float* __restrict__ out,
                        int ng) {
    int g = blockIdx.x * blockDim.x + threadIdx.x;
    if (g < ng) out[g] = g_gsum[g] / fmaxf(g_gcnt[g], 1.0f) + lb[0];
}

// ---------------- launch ------------------------------------------------------
extern "C" void kernel_launch(void* const* d_in, const int* in_sizes, int n_in,
                              void* d_out, int out_size) {
    const float* x     = (const float*)d_in[0];
    const float* W1    = (const float*)d_in[1];
    const float* b1    = (const float*)d_in[2];
    const float* W2    = (const float*)d_in[3];
    const float* b2    = (const float*)d_in[4];
    const float* W3    = (const float*)d_in[5];
    const float* b3    = (const float*)d_in[6];
    const float* lin_W = (const float*)d_in[7];
    const float* lin_b = (const float*)d_in[8];
    const void*  ei    = (const void*)d_in[9];
    const void*  batch = (const void*)d_in[10];
    float* out = (float*)d_out;

    const int n = in_sizes[0] / DIM;       // 50000
    const int E = in_sizes[9] / 2;         // 800000

    const int TB = 256;
    const int gN = (n + TB - 1) / TB;               // node grid
    const int gE = (E + TB - 1) / TB;               // edge grid
    const int gW = (n * 32 + TB - 1) / TB;          // warp-per-node grid

    k_zero_detect<<<gN, TB>>>(ei, n);
    k_hist<<<gE, TB>>>(ei, E);
    k_dinv<<<gN, TB>>>(batch, n);
    k_scan<<<1, 1024>>>(n);
    k_csr<<<gE, TB>>>(E);

    const int gG = (n + 63) / 64;
    // layer 1
    k_gemm<<<gG, TB>>>(x, W1, g_h, n);
    k_agg<1><<<gW, TB>>>(g_h, b1, g_f, n);
    // layer 2
    k_gemm<<<gG, TB>>>(g_f, W2, g_h, n);
    k_agg<1><<<gW, TB>>>(g_h, b2, g_f, n);
    // layer 3 fused with linear head + pooling sums
    k_gemm<<<gG, TB>>>(g_f, W3, g_h, n);
    k_agg_final<<<gW, TB>>>(g_h, b3, lin_W, batch, n);

    k_final<<<(out_size + TB - 1) / TB, TB>>>(lin_b, out, out_size);
}

// round 2
// speedup vs baseline: 1.0047x; 1.0047x over previous
#include <cuda_runtime.h>

#define NMAX 50000
#define EMAX 800000
#define DIM 64
#define NGR 512

// ---------------- scratch (device globals: no allocation allowed) -----------
__device__ int   g_is64;
__device__ int   g_deg[NMAX];        // per-target real-edge count
__device__ int   g_off[NMAX + 1];    // CSR offsets
__device__ int   g_cur[NMAX];        // scatter cursors
__device__ float g_dinv[NMAX];       // 1/sqrt(deg+1)
__device__ int   g_row[EMAX];
__device__ int   g_col[EMAX];
__device__ int   g_src[EMAX];        // CSR-sorted source node
__device__ float g_nrm[EMAX];        // CSR-sorted edge norm
__device__ float g_h[NMAX * DIM];    // GEMM output (pre-aggregation)
__device__ float g_f[NMAX * DIM];    // aggregated features (next layer input)
__device__ float g_gsum[NGR];
__device__ float g_gcnt[NGR];

// ---------------- K0: zero scratch + detect index dtype ---------------------
__global__ void k_zero_detect(const void* ei, int n) {
    int i = blockIdx.x * blockDim.x + threadIdx.x;
    if (i < n) { g_deg[i] = 0; g_cur[i] = 0; }
    if (i < NGR) { g_gsum[i] = 0.f; g_gcnt[i] = 0.f; }
    if (i == 0) {
        // int64 little-endian: high 32-bit word of every (small, positive)
        // index is 0. For int32 data the odd words are uniform in [0,50000).
        const int* p = (const int*)ei;
        int is64 = 1;
        for (int k = 0; k < 512; k++) {
            if (p[2 * k + 1] != 0) { is64 = 0; break; }
        }
        g_is64 = is64;
    }
}

// ---------------- K1: convert indices + degree histogram --------------------
__global__ void k_hist(const void* ei, int E) {
    int e = blockIdx.x * blockDim.x + threadIdx.x;
    if (e >= E) return;
    int r, c;
    if (g_is64) {
        const long long* p = (const long long*)ei;
        r = (int)p[e]; c = (int)p[E + e];
    } else {
        const int* p = (const int*)ei;
        r = p[e]; c = p[E + e];
    }
    g_row[e] = r;
    g_col[e] = c;
    atomicAdd(&g_deg[c], 1);
}

// ---------------- K2: dinv + per-graph node counts ---------------------------
__global__ void k_dinv(const void* batch, int n) {
    int i = blockIdx.x * blockDim.x + threadIdx.x;
    if (i >= n) return;
    g_dinv[i] = rsqrtf((float)(g_deg[i] + 1));   // +1 = self-loop
    int b = g_is64 ? (int)((const long long*)batch)[i]
                   : ((const int*)batch)[i];
    atomicAdd(&g_gcnt[b], 1.0f);
}

// ---------------- K3: single-block exclusive scan of g_deg -> g_off ---------
__global__ void k_scan(int n) {
    __shared__ int sh[1024];
    const int tid = threadIdx.x;
    const int chunk = (n + 1023) / 1024;
    const int beg = tid * chunk;
    const int end = min(beg + chunk, n);
    int s = 0;
    for (int i = beg; i < end; i++) s += g_deg[i];
    sh[tid] = s;
    __syncthreads();
    // Hillis-Steele inclusive scan over 1024 partials
    for (int d = 1; d < 1024; d <<= 1) {
        int v = (tid >= d) ? sh[tid - d] : 0;
        __syncthreads();
        sh[tid] += v;
        __syncthreads();
    }
    int pre = (tid == 0) ? 0 : sh[tid - 1];
    for (int i = beg; i < end; i++) {
        g_off[i] = pre;
        pre += g_deg[i];
    }
    if (beg < n && end == n) g_off[n] = pre;
}

// ---------------- K4: scatter edges into CSR slots ---------------------------
__global__ void k_csr(int E) {
    int e = blockIdx.x * blockDim.x + threadIdx.x;
    if (e >= E) return;
    int c = g_col[e];
    int r = g_row[e];
    int pos = g_off[c] + atomicAdd(&g_cur[c], 1);
    g_src[pos] = r;
    g_nrm[pos] = g_dinv[r] * g_dinv[c];
}

// ---------------- K5: GEMM  H = X @ W  (X: [n,64], W: [64,64]) --------------
// 256 threads, 64 nodes per block. Thread tile: 2 nodes x 8 cols.
__global__ __launch_bounds__(256) void k_gemm(const float* __restrict__ X,
                                              const float* __restrict__ W,
                                              float* __restrict__ H, int n) {
    __shared__ float xs[64][65];   // padded: conflict-free column reads
    __shared__ float ws[64][64];
    const int tid = threadIdx.x;
    const int n0 = blockIdx.x * 64;

    // stage W (4096 floats)
    for (int i = tid; i < 64 * 16; i += 256)
        ((float4*)ws)[i] = ((const float4*)W)[i];
    // stage X tile (64 rows x 16 float4)
    for (int i = tid; i < 64 * 16; i += 256) {
        int r = i >> 4, kq = (i & 15) << 2;
        int node = n0 + r;
        float4 v = (node < n) ? ((const float4*)(X + (size_t)node * DIM))[i & 15]
                              : make_float4(0.f, 0.f, 0.f, 0.f);
        xs[r][kq] = v.x; xs[r][kq + 1] = v.y; xs[r][kq + 2] = v.z; xs[r][kq + 3] = v.w;
    }
    __syncthreads();

    const int cg = tid & 7;    // 8 column groups of 8
    const int ng = tid >> 3;   // 32 node groups of 2
    float acc[2][8];
#pragma unroll
    for (int i = 0; i < 2; i++)
#pragma unroll
        for (int j = 0; j < 8; j++) acc[i][j] = 0.f;

#pragma unroll 8
    for (int k = 0; k < 64; k++) {
        float4 w0 = *(float4*)&ws[k][cg * 8];
        float4 w1 = *(float4*)&ws[k][cg * 8 + 4];
#pragma unroll
        for (int i = 0; i < 2; i++) {
            float xv = xs[ng * 2 + i][k];
            acc[i][0] += xv * w0.x; acc[i][1] += xv * w0.y;
            acc[i][2] += xv * w0.z; acc[i][3] += xv * w0.w;
            acc[i][4] += xv * w1.x; acc[i][5] += xv * w1.y;
            acc[i][6] += xv * w1.z; acc[i][7] += xv * w1.w;
        }
    }
#pragma unroll
    for (int i = 0; i < 2; i++) {
        int node = n0 + ng * 2 + i;
        if (node < n) {
            float4 o0 = make_float4(acc[i][0], acc[i][1], acc[i][2], acc[i][3]);
            float4 o1 = make_float4(acc[i][4], acc[i][5], acc[i][6], acc[i][7]);
            float4* dst = (float4*)(H + (size_t)node * DIM);
            dst[cg * 2] = o0;
            dst[cg * 2 + 1] = o1;
        }
    }
}

// ---------------- K6: gather-aggregation, one warp per node -----------------
// F[c] = relu?( b + dinv[c]^2 * H[c] + sum_e nrm[e] * H[src[e]] )
template <int RELU>
__global__ __launch_bounds__(256) void k_agg(const float* __restrict__ H,
                                             const float* __restrict__ bias,
                                             float* __restrict__ F, int n) {
    int c = (blockIdx.x * blockDim.x + threadIdx.x) >> 5;
    int lane = threadIdx.x & 31;
    if (c >= n) return;

    float2 acc = ((const float2*)bias)[lane];
    float di = g_dinv[c];
    float s = di * di;
    float2 hc = *(const float2*)(H + (size_t)c * DIM + 2 * lane);
    acc.x += s * hc.x; acc.y += s * hc.y;

    int e = g_off[c];
    const int end = g_off[c + 1];
    for (; e + 1 < end; e += 2) {
        int s0 = g_src[e], s1 = g_src[e + 1];
        float w0 = g_nrm[e], w1 = g_nrm[e + 1];
        float2 a = *(const float2*)(H + (size_t)s0 * DIM + 2 * lane);
        float2 b = *(const float2*)(H + (size_t)s1 * DIM + 2 * lane);
        acc.x += w0 * a.x + w1 * b.x;
        acc.y += w0 * a.y + w1 * b.y;
    }
    if (e < end) {
        int s0 = g_src[e];
        float w0 = g_nrm[e];
        float2 a = *(const float2*)(H + (size_t)s0 * DIM + 2 * lane);
        acc.x += w0 * a.x; acc.y += w0 * a.y;
    }
    if (RELU) { acc.x = fmaxf(acc.x, 0.f); acc.y = fmaxf(acc.y, 0.f); }
    *(float2*)(F + (size_t)c * DIM + 2 * lane) = acc;
}

// ---------------- K6f: final layer fused with lin head + pooling sums -------
__global__ __launch_bounds__(256) void k_agg_final(const float* __restrict__ H,
                                                   const float* __restrict__ bias,
                                                   const float* __restrict__ lw,
                                                   const void* __restrict__ batch,
                                                   int n) {
    int c = (blockIdx.x * blockDim.x + threadIdx.x) >> 5;
    int lane = threadIdx.x & 31;
    if (c >= n) return;

    float2 acc = ((const float2*)bias)[lane];
    float di = g_dinv[c];
    float s = di * di;
    float2 hc = *(const float2*)(H + (size_t)c * DIM + 2 * lane);
    acc.x += s * hc.x; acc.y += s * hc.y;

    int e = g_off[c];
    const int end = g_off[c + 1];
    for (; e + 1 < end; e += 2) {
        int s0 = g_src[e], s1 = g_src[e + 1];
        float w0 = g_nrm[e], w1 = g_nrm[e + 1];
        float2 a = *(const float2*)(H + (size_t)s0 * DIM + 2 * lane);
        float2 b = *(const float2*)(H + (size_t)s1 * DIM + 2 * lane);
        acc.x += w0 * a.x + w1 * b.x;
        acc.y += w0 * a.y + w1 * b.y;
    }
    if (e < end) {
        int s0 = g_src[e];
        float w0 = g_nrm[e];
        float2 a = *(const float2*)(H + (size_t)s0 * DIM + 2 * lane);
        acc.x += w0 * a.x; acc.y += w0 * a.y;
    }

    float2 w = ((const float2*)lw)[lane];
    float p = acc.x * w.x + acc.y * w.y;
#pragma unroll
    for (int o = 16; o; o >>= 1) p += __shfl_xor_sync(0xFFFFFFFFu, p, o);
    if (lane == 0) {
        int b = g_is64 ? (int)((const long long*)batch)[c]
                       : ((const int*)batch)[c];
        atomicAdd(&g_gsum[b], p);
    }
}

// ---------------- K7: finalize output ---------------------------------------
__global__ void k_final(const float* __restrict__ lb, float* __restrict__ out,
                        int ng) {
    int g = blockIdx.x * blockDim.x + threadIdx.x;
    if (g < ng) out[g] = g_gsum[g] / fmaxf(g_gcnt[g], 1.0f) + lb[0];
}

// ---------------- launch ------------------------------------------------------
extern "C" void kernel_launch(void* const* d_in, const int* in_sizes, int n_in,
                              void* d_out, int out_size) {
    const float* x     = (const float*)d_in[0];
    const float* W1    = (const float*)d_in[1];
    const float* b1    = (const float*)d_in[2];
    const float* W2    = (const float*)d_in[3];
    const float* b2    = (const float*)d_in[4];
    const float* W3    = (const float*)d_in[5];
    const float* b3    = (const float*)d_in[6];
    const float* lin_W = (const float*)d_in[7];
    const float* lin_b = (const float*)d_in[8];
    const void*  ei    = (const void*)d_in[9];
    const void*  batch = (const void*)d_in[10];
    float* out = (float*)d_out;

    const int n = in_sizes[0] / DIM;       // 50000
    const int E = in_sizes[9] / 2;         // 800000

    const int TB = 256;
    const int gN = (n + TB - 1) / TB;               // node grid
    const int gE = (E + TB - 1) / TB;               // edge grid
    const int gW = (n * 32 + TB - 1) / TB;          // warp-per-node grid

    k_zero_detect<<<gN, TB>>>(ei, n);
    k_hist<<<gE, TB>>>(ei, E);
    k_dinv<<<gN, TB>>>(batch, n);
    k_scan<<<1, 1024>>>(n);
    k_csr<<<gE, TB>>>(E);

    const int gG = (n + 63) / 64;
    // layer 1
    k_gemm<<<gG, TB>>>(x, W1, g_h, n);
    k_agg<1><<<gW, TB>>>(g_h, b1, g_f, n);
    // layer 2
    k_gemm<<<gG, TB>>>(g_f, W2, g_h, n);
    k_agg<1><<<gW, TB>>>(g_h, b2, g_f, n);
    // layer 3 fused with linear head + pooling sums
    k_gemm<<<gG, TB>>>(g_f, W3, g_h, n);
    k_agg_final<<<gW, TB>>>(g_h, b3, lin_W, batch, n);

    k_final<<<(out_size + TB - 1) / TB, TB>>>(lin_b, out, out_size);
}

// round 3
// speedup vs baseline: 1.0056x; 1.0008x over previous
#include <cuda_runtime.h>

#define NMAX 50000
#define EMAX 800000
#define DIM 64
#define NGR 512

// ---------------- scratch (device globals: no allocation allowed) -----------
__device__ int   g_is64;
__device__ int   g_deg[NMAX];        // per-target real-edge count
__device__ int   g_off[NMAX + 1];    // CSR offsets
__device__ int   g_cur[NMAX];        // scatter cursors
__device__ float g_dinv[NMAX];       // 1/sqrt(deg+1)
__device__ int   g_row[EMAX];
__device__ int   g_col[EMAX];
__device__ int   g_src[EMAX];        // CSR-sorted source node
__device__ float g_nrm[EMAX];        // CSR-sorted edge norm
__device__ float g_h[NMAX * DIM];    // GEMM output (pre-aggregation)
__device__ float g_f[NMAX * DIM];    // aggregated features (next layer input)
__device__ float g_gsum[NGR];
__device__ float g_gcnt[NGR];

// ---------------- K0: zero scratch + detect index dtype ---------------------
__global__ void k_zero_detect(const void* ei, int n) {
    int i = blockIdx.x * blockDim.x + threadIdx.x;
    if (i < n) { g_deg[i] = 0; g_cur[i] = 0; }
    if (i < NGR) { g_gsum[i] = 0.f; g_gcnt[i] = 0.f; }
    if (i == 0) {
        // int64 little-endian: high 32-bit word of every (small, positive)
        // index is 0. For int32 data the odd words are uniform in [0,50000).
        const int* p = (const int*)ei;
        int is64 = 1;
        for (int k = 0; k < 512; k++) {
            if (p[2 * k + 1] != 0) { is64 = 0; break; }
        }
        g_is64 = is64;
    }
}

// ---------------- K1: convert indices + degree histogram --------------------
__global__ void k_hist(const void* ei, int E) {
    int e = blockIdx.x * blockDim.x + threadIdx.x;
    if (e >= E) return;
    int r, c;
    if (g_is64) {
        const long long* p = (const long long*)ei;
        r = (int)p[e]; c = (int)p[E + e];
    } else {
        const int* p = (const int*)ei;
        r = p[e]; c = p[E + e];
    }
    g_row[e] = r;
    g_col[e] = c;
    atomicAdd(&g_deg[c], 1);
}

// ---------------- K2: dinv + per-graph node counts ---------------------------
__global__ void k_dinv(const void* batch, int n) {
    int i = blockIdx.x * blockDim.x + threadIdx.x;
    if (i >= n) return;
    g_dinv[i] = rsqrtf((float)(g_deg[i] + 1));   // +1 = self-loop
    int b = g_is64 ? (int)((const long long*)batch)[i]
                   : ((const int*)batch)[i];
    atomicAdd(&g_gcnt[b], 1.0f);
}

// ---------------- K3: single-block exclusive scan of g_deg -> g_off ---------
__global__ void k_scan(int n) {
    __shared__ int sh[1024];
    const int tid = threadIdx.x;
    const int chunk = (n + 1023) / 1024;
    const int beg = tid * chunk;
    const int end = min(beg + chunk, n);
    int s = 0;
    for (int i = beg; i < end; i++) s += g_deg[i];
    sh[tid] = s;
    __syncthreads();
    // Hillis-Steele inclusive scan over 1024 partials
    for (int d = 1; d < 1024; d <<= 1) {
        int v = (tid >= d) ? sh[tid - d] : 0;
        __syncthreads();
        sh[tid] += v;
        __syncthreads();
    }
    int pre = (tid == 0) ? 0 : sh[tid - 1];
    for (int i = beg; i < end; i++) {
        g_off[i] = pre;
        pre += g_deg[i];
    }
    if (beg < n && end == n) g_off[n] = pre;
}

// ---------------- K4: scatter edges into CSR slots ---------------------------
__global__ void k_csr(int E) {
    int e = blockIdx.x * blockDim.x + threadIdx.x;
    if (e >= E) return;
    int c = g_col[e];
    int r = g_row[e];
    int pos = g_off[c] + atomicAdd(&g_cur[c], 1);
    g_src[pos] = r;
    g_nrm[pos] = g_dinv[r] * g_dinv[c];
}

// ---------------- K5: GEMM  H = X @ W  (X: [n,64], W: [64,64]) --------------
// 256 threads, 64 nodes per block. Thread tile: 2 nodes x 8 cols.
__global__ __launch_bounds__(256) void k_gemm(const float* __restrict__ X,
                                              const float* __restrict__ W,
                                              float* __restrict__ H, int n) {
    __shared__ float xs[64][65];   // padded: conflict-free column reads
    __shared__ float ws[64][64];
    const int tid = threadIdx.x;
    const int n0 = blockIdx.x * 64;

    // stage W (4096 floats)
    for (int i = tid; i < 64 * 16; i += 256)
        ((float4*)ws)[i] = ((const float4*)W)[i];
    // stage X tile (64 rows x 16 float4)
    for (int i = tid; i < 64 * 16; i += 256) {
        int r = i >> 4, kq = (i & 15) << 2;
        int node = n0 + r;
        float4 v = (node < n) ? ((const float4*)(X + (size_t)node * DIM))[i & 15]
                              : make_float4(0.f, 0.f, 0.f, 0.f);
        xs[r][kq] = v.x; xs[r][kq + 1] = v.y; xs[r][kq + 2] = v.z; xs[r][kq + 3] = v.w;
    }
    __syncthreads();

    const int cg = tid & 7;    // 8 column groups of 8
    const int ng = tid >> 3;   // 32 node groups of 2
    float acc[2][8];
#pragma unroll
    for (int i = 0; i < 2; i++)
#pragma unroll
        for (int j = 0; j < 8; j++) acc[i][j] = 0.f;

#pragma unroll 8
    for (int k = 0; k < 64; k++) {
        float4 w0 = *(float4*)&ws[k][cg * 8];
        float4 w1 = *(float4*)&ws[k][cg * 8 + 4];
#pragma unroll
        for (int i = 0; i < 2; i++) {
            float xv = xs[ng * 2 + i][k];
            acc[i][0] += xv * w0.x; acc[i][1] += xv * w0.y;
            acc[i][2] += xv * w0.z; acc[i][3] += xv * w0.w;
            acc[i][4] += xv * w1.x; acc[i][5] += xv * w1.y;
            acc[i][6] += xv * w1.z; acc[i][7] += xv * w1.w;
        }
    }
#pragma unroll
    for (int i = 0; i < 2; i++) {
        int node = n0 + ng * 2 + i;
        if (node < n) {
            float4 o0 = make_float4(acc[i][0], acc[i][1], acc[i][2], acc[i][3]);
            float4 o1 = make_float4(acc[i][4], acc[i][5], acc[i][6], acc[i][7]);
            float4* dst = (float4*)(H + (size_t)node * DIM);
            dst[cg * 2] = o0;
            dst[cg * 2 + 1] = o1;
        }
    }
}

// ---------------- K6: gather-aggregation, one warp per node -----------------
// F[c] = relu?( b + dinv[c]^2 * H[c] + sum_e nrm[e] * H[src[e]] )
template <int RELU>
__global__ __launch_bounds__(256) void k_agg(const float* __restrict__ H,
                                             const float* __restrict__ bias,
                                             float* __restrict__ F, int n) {
    int c = (blockIdx.x * blockDim.x + threadIdx.x) >> 5;
    int lane = threadIdx.x & 31;
    if (c >= n) return;

    float2 acc = ((const float2*)bias)[lane];
    float di = g_dinv[c];
    float s = di * di;
    float2 hc = *(const float2*)(H + (size_t)c * DIM + 2 * lane);
    acc.x += s * hc.x; acc.y += s * hc.y;

    int e = g_off[c];
    const int end = g_off[c + 1];
    for (; e + 1 < end; e += 2) {
        int s0 = g_src[e], s1 = g_src[e + 1];
        float w0 = g_nrm[e], w1 = g_nrm[e + 1];
        float2 a = *(const float2*)(H + (size_t)s0 * DIM + 2 * lane);
        float2 b = *(const float2*)(H + (size_t)s1 * DIM + 2 * lane);
        acc.x += w0 * a.x + w1 * b.x;
        acc.y += w0 * a.y + w1 * b.y;
    }
    if (e < end) {
        int s0 = g_src[e];
        float w0 = g_nrm[e];
        float2 a = *(const float2*)(H + (size_t)s0 * DIM + 2 * lane);
        acc.x += w0 * a.x; acc.y += w0 * a.y;
    }
    if (RELU) { acc.x = fmaxf(acc.x, 0.f); acc.y = fmaxf(acc.y, 0.f); }
    *(float2*)(F + (size_t)c * DIM + 2 * lane) = acc;
}

// ---------------- K6f: final layer fused with lin head + pooling sums -------
__global__ __launch_bounds__(256) void k_agg_final(const float* __restrict__ H,
                                                   const float* __restrict__ bias,
                                                   const float* __restrict__ lw,
                                                   const void* __restrict__ batch,
                                                   int n) {
    int c = (blockIdx.x * blockDim.x + threadIdx.x) >> 5;
    int lane = threadIdx.x & 31;
    if (c >= n) return;

    float2 acc = ((const float2*)bias)[lane];
    float di = g_dinv[c];
    float s = di * di;
    float2 hc = *(const float2*)(H + (size_t)c * DIM + 2 * lane);
    acc.x += s * hc.x; acc.y += s * hc.y;

    int e = g_off[c];
    const int end = g_off[c + 1];
    for (; e + 1 < end; e += 2) {
        int s0 = g_src[e], s1 = g_src[e + 1];
        float w0 = g_nrm[e], w1 = g_nrm[e + 1];
        float2 a = *(const float2*)(H + (size_t)s0 * DIM + 2 * lane);
        float2 b = *(const float2*)(H + (size_t)s1 * DIM + 2 * lane);
        acc.x += w0 * a.x + w1 * b.x;
        acc.y += w0 * a.y + w1 * b.y;
    }
    if (e < end) {
        int s0 = g_src[e];
        float w0 = g_nrm[e];
        float2 a = *(const float2*)(H + (size_t)s0 * DIM + 2 * lane);
        acc.x += w0 * a.x; acc.y += w0 * a.y;
    }

    float2 w = ((const float2*)lw)[lane];
    float p = acc.x * w.x + acc.y * w.y;
#pragma unroll
    for (int o = 16; o; o >>= 1) p += __shfl_xor_sync(0xFFFFFFFFu, p, o);
    if (lane == 0) {
        int b = g_is64 ? (int)((const long long*)batch)[c]
                       : ((const int*)batch)[c];
        atomicAdd(&g_gsum[b], p);
    }
}

// ---------------- K7: finalize output ---------------------------------------
__global__ void k_final(const float* __restrict__ lb, float* __restrict__ out,
                        int ng) {
    int g = blockIdx.x * blockDim.x + threadIdx.x;
    if (g < ng) out[g] = g_gsum[g] / fmaxf(g_gcnt[g], 1.0f) + lb[0];
}

// ---------------- launch ------------------------------------------------------
extern "C" void kernel_launch(void* const* d_in, const int* in_sizes, int n_in,
                              void* d_out, int out_size) {
    const float* x     = (const float*)d_in[0];
    const float* W1    = (const float*)d_in[1];
    const float* b1    = (const float*)d_in[2];
    const float* W2    = (const float*)d_in[3];
    const float* b2    = (const float*)d_in[4];
    const float* W3    = (const float*)d_in[5];
    const float* b3    = (const float*)d_in[6];
    const float* lin_W = (const float*)d_in[7];
    const float* lin_b = (const float*)d_in[8];
    const void*  ei    = (const void*)d_in[9];
    const void*  batch = (const void*)d_in[10];
    float* out = (float*)d_out;

    const int n = in_sizes[0] / DIM;       // 50000
    const int E = in_sizes[9] / 2;         // 800000

    const int TB = 256;
    const int gN = (n + TB - 1) / TB;               // node grid
    const int gE = (E + TB - 1) / TB;               // edge grid
    const int gW = (n * 32 + TB - 1) / TB;          // warp-per-node grid

    k_zero_detect<<<gN, TB>>>(ei, n);
    k_hist<<<gE, TB>>>(ei, E);
    k_dinv<<<gN, TB>>>(batch, n);
    k_scan<<<1, 1024>>>(n);
    k_csr<<<gE, TB>>>(E);

    const int gG = (n + 63) / 64;
    // layer 1
    k_gemm<<<gG, TB>>>(x, W1, g_h, n);
    k_agg<1><<<gW, TB>>>(g_h, b1, g_f, n);
    // layer 2
    k_gemm<<<gG, TB>>>(g_f, W2, g_h, n);
    k_agg<1><<<gW, TB>>>(g_h, b2, g_f, n);
    // layer 3 fused with linear head + pooling sums
    k_gemm<<<gG, TB>>>(g_f, W3, g_h, n);
    k_agg_final<<<gW, TB>>>(g_h, b3, lin_W, batch, n);

    k_final<<<(out_size + TB - 1) / TB, TB>>>(lin_b, out, out_size);
}